// round 1
// baseline (speedup 1.0000x reference)
#include <cuda_runtime.h>

// ConvSepKanCell: per-pixel dynamic KAN.
// x: (2, 16, 128, 128) f32   w: (2, 3328, 128, 128) f32   out: (2, 16, 128, 128) f32
// Param layout along dim-1 of w (per pixel):
//   [0, 2816)      coef[i][o][m]  (16 x 16 x 11), index = i*176 + o*11 + m
//   [2816, 3072)   uw[i][o]       (16 x 16)
//   [3072, 3328)   rw[i][o]       (16 x 16)
// y[o] = sum_i uw[i][o] * (sum_m coef[i][o][m]*B3_m(x_i)) + rw[i][o]*silu(x_i)

#define HW      16384
#define INC     16
#define OUTC    16
#define COEFM   11
#define SIZE_W  3328
#define I0      2816      // 16*16*11
#define I1      3072      // I0 + 256
#define OSPLIT  4         // outputs per thread = OUTC / OSPLIT = 4

__global__ __launch_bounds__(256)
void kan_kernel(const float* __restrict__ x,
                const float* __restrict__ w,
                float* __restrict__ out)
{
    const int pix   = blockIdx.x * 256 + threadIdx.x;   // 0..32767
    const int slice = blockIdx.y;                       // 0..3 -> outputs slice*4 .. +4
    const int b  = pix >> 14;
    const int hw = pix & (HW - 1);

    const float* wp = w + (size_t)b * SIZE_W * HW + hw;
    const float* xp = x + (size_t)b * INC * HW + hw;

    // bases for this slice's 4 outputs; advance per input i
    const float* cp = wp + (size_t)(slice * 4 * COEFM) * HW;
    const float* up = wp + (size_t)(I0 + slice * 4) * HW;
    const float* rp = wp + (size_t)(I1 + slice * 4) * HW;

    float y0 = 0.f, y1 = 0.f, y2 = 0.f, y3 = 0.f;

    for (int i = 0; i < INC; ++i) {
        const float xi = *xp;
        xp += HW;

        // ---- Cox-de Boor, K=3, uniform knots grid[j] = 0.25j - 1.75 (exact fp32) ----
        float bb[14];
        #pragma unroll
        for (int j = 0; j < 14; ++j) {
            const float gj = 0.25f * (float)j - 1.75f;       // exact quarters
            bb[j] = (xi >= gj && xi < gj + 0.25f) ? 1.f : 0.f;
        }
        // t - j == (x - grid[j]) / h  with t = 4x + 7
        const float t = fmaf(xi, 4.0f, 7.0f);
        #pragma unroll
        for (int p = 1; p <= 3; ++p) {
            const float invp = 1.0f / (float)p;
            #pragma unroll
            for (int j = 0; j < 14 - p; ++j) {
                const float left  = (t - (float)j) * invp;
                const float right = ((float)(j + p + 1) - t) * invp;
                bb[j] = left * bb[j] + right * bb[j + 1];
            }
        }
        const float sx = xi / (1.0f + __expf(-xi));          // silu

        // ---- spline contraction for this slice's 4 outputs ----
        float s0 = 0.f, s1 = 0.f, s2 = 0.f, s3 = 0.f;
        #pragma unroll
        for (int m = 0; m < COEFM; ++m) {
            const float bm = bb[m];
            s0 = fmaf(cp[(0 * COEFM + m) * HW], bm, s0);
            s1 = fmaf(cp[(1 * COEFM + m) * HW], bm, s1);
            s2 = fmaf(cp[(2 * COEFM + m) * HW], bm, s2);
            s3 = fmaf(cp[(3 * COEFM + m) * HW], bm, s3);
        }
        y0 += up[0 * HW] * s0 + rp[0 * HW] * sx;
        y1 += up[1 * HW] * s1 + rp[1 * HW] * sx;
        y2 += up[2 * HW] * s2 + rp[2 * HW] * sx;
        y3 += up[3 * HW] * s3 + rp[3 * HW] * sx;

        cp += (size_t)(OUTC * COEFM) * HW;
        up += (size_t)OUTC * HW;
        rp += (size_t)OUTC * HW;
    }

    float* op = out + (size_t)b * OUTC * HW + (size_t)(slice * 4) * HW + hw;
    op[0 * HW] = y0;
    op[1 * HW] = y1;
    op[2 * HW] = y2;
    op[3 * HW] = y3;
}

extern "C" void kernel_launch(void* const* d_in, const int* in_sizes, int n_in,
                              void* d_out, int out_size)
{
    const float* x = (const float*)d_in[0];
    const float* w = (const float*)d_in[1];
    float* out = (float*)d_out;

    dim3 grid(32768 / 256, OSPLIT);   // (128, 4) = 512 blocks
    kan_kernel<<<grid, 256>>>(x, w, out);
}

// round 2
// speedup vs baseline: 1.0232x; 1.0232x over previous
#include <cuda_runtime.h>

// ConvSepKanCell: per-pixel dynamic KAN.
// x: (2, 16, 128, 128) f32   w: (2, 3328, 128, 128) f32   out: (2, 16, 128, 128) f32
// Param layout along dim-1 of w (per pixel):
//   [0, 2816)      coef[i][o][m]  (16 x 16 x 11), index = i*176 + o*11 + m
//   [2816, 3072)   uw[i][o]       (16 x 16)
//   [3072, 3328)   rw[i][o]       (16 x 16)
// y[o] = sum_i uw[i][o] * (sum_m coef[i][o][m]*B3_m(x_i)) + rw[i][o]*silu(x_i)

#define HW      16384
#define INC     16
#define OUTC    16
#define COEFM   11
#define SIZE_W  3328
#define I0      2816      // 16*16*11
#define I1      3072      // I0 + 256
#define OSPLIT  8         // output slices; outputs per thread = OUTC/OSPLIT = 2

__global__ __launch_bounds__(256, 7)
void kan_kernel(const float* __restrict__ x,
                const float* __restrict__ w,
                float* __restrict__ out)
{
    const int pix   = blockIdx.x * 256 + threadIdx.x;   // 0..32767
    const int slice = blockIdx.y;                       // 0..7 -> outputs slice*2 .. +2
    const int b  = pix >> 14;
    const int hw = pix & (HW - 1);

    const float* wp = w + (size_t)b * SIZE_W * HW + hw;
    const float* xp = x + (size_t)b * INC * HW + hw;

    const float* cp = wp + (size_t)(slice * 2 * COEFM) * HW;
    const float* up = wp + (size_t)(I0 + slice * 2) * HW;
    const float* rp = wp + (size_t)(I1 + slice * 2) * HW;

    float y0 = 0.f, y1 = 0.f;

    for (int i = 0; i < INC; ++i) {
        const float xi = *xp;
        xp += HW;

        // ---- Cox-de Boor, K=3, uniform knots grid[j] = 0.25j - 1.75 (exact fp32) ----
        float bb[14];
        #pragma unroll
        for (int j = 0; j < 14; ++j) {
            const float gj = 0.25f * (float)j - 1.75f;       // exact quarters
            bb[j] = (xi >= gj && xi < gj + 0.25f) ? 1.f : 0.f;
        }
        // t - j == (x - grid[j]) / h  with t = 4x + 7
        const float t = fmaf(xi, 4.0f, 7.0f);
        #pragma unroll
        for (int p = 1; p <= 3; ++p) {
            const float invp = 1.0f / (float)p;
            #pragma unroll
            for (int j = 0; j < 14 - p; ++j) {
                const float left  = (t - (float)j) * invp;
                const float right = ((float)(j + p + 1) - t) * invp;
                bb[j] = left * bb[j] + right * bb[j + 1];
            }
        }
        const float sx = xi / (1.0f + __expf(-xi));          // silu

        // ---- spline contraction for this slice's 2 outputs ----
        float s0 = 0.f, s1 = 0.f;
        #pragma unroll
        for (int m = 0; m < COEFM; ++m) {
            const float bm = bb[m];
            s0 = fmaf(cp[(0 * COEFM + m) * HW], bm, s0);
            s1 = fmaf(cp[(1 * COEFM + m) * HW], bm, s1);
        }
        y0 += up[0 * HW] * s0 + rp[0 * HW] * sx;
        y1 += up[1 * HW] * s1 + rp[1 * HW] * sx;

        cp += (size_t)(OUTC * COEFM) * HW;
        up += (size_t)OUTC * HW;
        rp += (size_t)OUTC * HW;
    }

    float* op = out + (size_t)b * OUTC * HW + (size_t)(slice * 2) * HW + hw;
    op[0 * HW] = y0;
    op[1 * HW] = y1;
}

extern "C" void kernel_launch(void* const* d_in, const int* in_sizes, int n_in,
                              void* d_out, int out_size)
{
    const float* x = (const float*)d_in[0];
    const float* w = (const float*)d_in[1];
    float* out = (float*)d_out;

    dim3 grid(32768 / 256, OSPLIT);   // (128, 8) = 1024 blocks
    kan_kernel<<<grid, 256>>>(x, w, out);
}

// round 3
// speedup vs baseline: 1.0530x; 1.0292x over previous
#include <cuda_runtime.h>

// ConvSepKanCell: per-pixel dynamic KAN — float2 (2 pixels/thread) version.
// x: (2, 16, 128, 128) f32   w: (2, 3328, 128, 128) f32   out: (2, 16, 128, 128) f32
// Param layout along dim-1 of w (per pixel):
//   [0, 2816)      coef[i][o][m]  (16 x 16 x 11)
//   [2816, 3072)   uw[i][o]
//   [3072, 3328)   rw[i][o]
// y[o] = sum_i uw[i][o] * (sum_m coef[i][o][m]*B3_m(x_i)) + rw[i][o]*silu(x_i)

#define HW      16384
#define HW2     8192      // float2 elements per image plane
#define INC     16
#define OUTC    16
#define COEFM   11
#define SIZE_W  3328
#define I0      2816
#define I1      3072
#define OSPLIT  8         // outputs per thread = 2

__device__ __forceinline__ float2 ldcs2(const float2* p) { return __ldcs(p); }

__global__ __launch_bounds__(256, 4)
void kan_kernel(const float* __restrict__ x,
                const float* __restrict__ w,
                float* __restrict__ out)
{
    const int t     = blockIdx.x * 256 + threadIdx.x;   // 0..16383 (float2 slots)
    const int slice = blockIdx.y;                       // 0..7 -> outputs slice*2..+2
    const int b   = t >> 13;                            // batch
    const int hw2 = t & (HW2 - 1);                      // float2 index in plane

    const float2* wp = (const float2*)(w + (size_t)b * SIZE_W * HW) + hw2;
    const float2* xp = (const float2*)(x + (size_t)b * INC * HW) + hw2;

    const float2* cp = wp + (size_t)(slice * 2 * COEFM) * HW2;
    const float2* up = wp + (size_t)(I0 + slice * 2) * HW2;
    const float2* rp = wp + (size_t)(I1 + slice * 2) * HW2;

    float y0a = 0.f, y0b = 0.f, y1a = 0.f, y1b = 0.f;

    for (int i = 0; i < INC; ++i) {
        const float2 xi = __ldg(xp);
        xp += HW2;

        // ---- Cox-de Boor, K=3, uniform knots grid[j] = 0.25j - 1.75 (exact fp32) ----
        float ba[14], bc[14];
        #pragma unroll
        for (int j = 0; j < 14; ++j) {
            const float gj = 0.25f * (float)j - 1.75f;
            ba[j] = (xi.x >= gj && xi.x < gj + 0.25f) ? 1.f : 0.f;
            bc[j] = (xi.y >= gj && xi.y < gj + 0.25f) ? 1.f : 0.f;
        }
        const float ta = fmaf(xi.x, 4.0f, 7.0f);
        const float tc = fmaf(xi.y, 4.0f, 7.0f);
        #pragma unroll
        for (int p = 1; p <= 3; ++p) {
            const float invp = 1.0f / (float)p;
            #pragma unroll
            for (int j = 0; j < 14 - p; ++j) {
                const float la = (ta - (float)j) * invp;
                const float ra = ((float)(j + p + 1) - ta) * invp;
                ba[j] = la * ba[j] + ra * ba[j + 1];
                const float lc = (tc - (float)j) * invp;
                const float rc = ((float)(j + p + 1) - tc) * invp;
                bc[j] = lc * bc[j] + rc * bc[j + 1];
            }
        }
        const float sxa = xi.x / (1.0f + __expf(-xi.x));
        const float sxb = xi.y / (1.0f + __expf(-xi.y));

        // ---- spline contraction for 2 outputs x 2 pixels ----
        float s0a = 0.f, s0b = 0.f, s1a = 0.f, s1b = 0.f;
        #pragma unroll
        for (int m = 0; m < COEFM; ++m) {
            const float2 c0 = ldcs2(cp + (0 * COEFM + m) * HW2);
            const float2 c1 = ldcs2(cp + (1 * COEFM + m) * HW2);
            s0a = fmaf(c0.x, ba[m], s0a);
            s0b = fmaf(c0.y, bc[m], s0b);
            s1a = fmaf(c1.x, ba[m], s1a);
            s1b = fmaf(c1.y, bc[m], s1b);
        }
        const float2 u0 = ldcs2(up + 0 * HW2);
        const float2 u1 = ldcs2(up + 1 * HW2);
        const float2 r0 = ldcs2(rp + 0 * HW2);
        const float2 r1 = ldcs2(rp + 1 * HW2);
        y0a += u0.x * s0a + r0.x * sxa;
        y0b += u0.y * s0b + r0.y * sxb;
        y1a += u1.x * s1a + r1.x * sxa;
        y1b += u1.y * s1b + r1.y * sxb;

        cp += (size_t)(OUTC * COEFM) * HW2;
        up += (size_t)OUTC * HW2;
        rp += (size_t)OUTC * HW2;
    }

    float2* op = (float2*)(out + (size_t)b * OUTC * HW) + (size_t)(slice * 2) * HW2 + hw2;
    op[0 * HW2] = make_float2(y0a, y0b);
    op[1 * HW2] = make_float2(y1a, y1b);
}

extern "C" void kernel_launch(void* const* d_in, const int* in_sizes, int n_in,
                              void* d_out, int out_size)
{
    const float* x = (const float*)d_in[0];
    const float* w = (const float*)d_in[1];
    float* out = (float*)d_out;

    dim3 grid(16384 / 256, OSPLIT);   // (64, 8) = 512 blocks
    kan_kernel<<<grid, 256>>>(x, w, out);
}